// round 7
// baseline (speedup 1.0000x reference)
#include <cuda_runtime.h>
#include <math.h>

// ---------------- scratch (no allocations allowed) ----------------
__device__ __align__(16) float g_sum[2][256];    // pass-1: sum(x)
__device__ __align__(16) float g_sumax[2][256];  // pass-2: sum(att*x)
__device__ __align__(16) float g_outv[2][256];   // pass-3: graph embedding (one head)
__device__ __align__(16) float g_h1[2][256];
__device__ __align__(16) float g_h2[2][256];
__device__ float g_wacc[16];                      // w_term + v_term accumulator
__device__ unsigned g_cnt[4];                     // last-block counters (sum g0/g1, attsum g0/g1)

__device__ __forceinline__ float sigf_fast(float z) { return 1.0f / (1.0f + __expf(-z)); }

static const int PGRID = 444;  // 148 SMs * 3 blocks -> guaranteed single wave at occ>=3

// ---------------- zero accumulators ----------------
__global__ void k_zero() {
    int t = threadIdx.x;
    g_sum[0][t] = 0.f;  g_sum[1][t] = 0.f;
    g_sumax[0][t] = 0.f; g_sumax[1][t] = 0.f;
    g_outv[0][t] = 0.f;  g_outv[1][t] = 0.f;
    if (t < 16) g_wacc[t] = 0.f;
    if (t < 4) g_cnt[t] = 0u;
}

// block-level 256-col reduction helper: per-warp float4 accumulators -> bacc -> global atomics
__device__ __forceinline__ void block_col_reduce(float bacc[256], int t, int lane,
                                                 float4 a0, float4 a1, float* gdst) {
    int c = lane * 4;
    atomicAdd(&bacc[c + 0], a0.x); atomicAdd(&bacc[c + 1], a0.y);
    atomicAdd(&bacc[c + 2], a0.z); atomicAdd(&bacc[c + 3], a0.w);
    atomicAdd(&bacc[128 + c + 0], a1.x); atomicAdd(&bacc[128 + c + 1], a1.y);
    atomicAdd(&bacc[128 + c + 2], a1.z); atomicAdd(&bacc[128 + c + 3], a1.w);
    __syncthreads();
    atomicAdd(&gdst[t], bacc[t]);
}

// ---------------- pass 1: column sum of x; last block computes h1 = tanh(mean @ W0) ----------------
__global__ void __launch_bounds__(256) k_sum(const float4* __restrict__ x, int nrows, int g,
                                             const float* __restrict__ W0, float invN) {
    __shared__ float bacc[256];
    __shared__ int isLast;
    int t = threadIdx.x;
    bacc[t] = 0.f;
    __syncthreads();
    int lane = t & 31;
    int gw = (blockIdx.x << 3) + (t >> 5);
    int nW = gridDim.x << 3;
    float4 a0 = make_float4(0.f,0.f,0.f,0.f), a1 = make_float4(0.f,0.f,0.f,0.f);
    int ngroups = nrows >> 2;
    for (int gi = gw; gi < ngroups; gi += nW) {
        const float4* base = x + (size_t)gi * 256;   // 4 rows * 64 float4
        float4 w00 = base[lane      ], w01 = base[lane +  32];
        float4 w10 = base[lane +  64], w11 = base[lane +  96];
        float4 w20 = base[lane + 128], w21 = base[lane + 160];
        float4 w30 = base[lane + 192], w31 = base[lane + 224];
        a0.x += (w00.x + w10.x) + (w20.x + w30.x);
        a0.y += (w00.y + w10.y) + (w20.y + w30.y);
        a0.z += (w00.z + w10.z) + (w20.z + w30.z);
        a0.w += (w00.w + w10.w) + (w20.w + w30.w);
        a1.x += (w01.x + w11.x) + (w21.x + w31.x);
        a1.y += (w01.y + w11.y) + (w21.y + w31.y);
        a1.z += (w01.z + w11.z) + (w21.z + w31.z);
        a1.w += (w01.w + w11.w) + (w21.w + w31.w);
    }
    int rem = nrows & 3;
    if (gw < rem) {
        const float4* base = x + (size_t)(ngroups * 4 + gw) * 64;
        float4 v0 = base[lane], v1 = base[lane + 32];
        a0.x += v0.x; a0.y += v0.y; a0.z += v0.z; a0.w += v0.w;
        a1.x += v1.x; a1.y += v1.y; a1.z += v1.z; a1.w += v1.w;
    }
    block_col_reduce(bacc, t, lane, a0, a1, g_sum[g]);

    // last finishing block computes h1 (replaces separate k_h launch)
    __threadfence();
    __syncthreads();
    if (t == 0) isLast = (atomicAdd(&g_cnt[g], 1u) == (unsigned)(gridDim.x - 1));
    __syncthreads();
    if (isLast) {
        __shared__ float tv[256];
        tv[t] = ((volatile float*)g_sum[g])[t] * invN;  // coherent: all adds fenced before counter
        __syncthreads();
        float acc = 0.f;
        #pragma unroll 8
        for (int i = 0; i < 256; ++i) acc = fmaf(tv[i], W0[i * 256 + t], acc);
        g_h1[g][t] = tanhf(acc);
    }
}

// ---------------- pass 2: att = sigmoid(x.h1); sum(att*x); last block computes h2 ----------------
__global__ void __launch_bounds__(256) k_attsum(const float4* __restrict__ x, int nrows, int g,
                                                const float* __restrict__ W0, float invN) {
    __shared__ float4 h1s[64];
    __shared__ float bacc[256];
    __shared__ int isLast;
    int t = threadIdx.x;
    bacc[t] = 0.f;
    if (t < 64) h1s[t] = ((const float4*)g_h1[g])[t];
    __syncthreads();
    int lane = t & 31;
    int gw = (blockIdx.x << 3) + (t >> 5);
    int nW = gridDim.x << 3;
    float4 ha = h1s[lane], hb = h1s[lane + 32];
    float4 a0 = make_float4(0.f,0.f,0.f,0.f), a1 = make_float4(0.f,0.f,0.f,0.f);
    int ngroups = nrows >> 2;
    for (int gi = gw; gi < ngroups; gi += nW) {
        const float4* base = x + (size_t)gi * 256;
        float4 w00 = base[lane      ], w01 = base[lane +  32];
        float4 w10 = base[lane +  64], w11 = base[lane +  96];
        float4 w20 = base[lane + 128], w21 = base[lane + 160];
        float4 w30 = base[lane + 192], w31 = base[lane + 224];
        float p0 = w00.x*ha.x + w00.y*ha.y + w00.z*ha.z + w00.w*ha.w
                 + w01.x*hb.x + w01.y*hb.y + w01.z*hb.z + w01.w*hb.w;
        float p1 = w10.x*ha.x + w10.y*ha.y + w10.z*ha.z + w10.w*ha.w
                 + w11.x*hb.x + w11.y*hb.y + w11.z*hb.z + w11.w*hb.w;
        float p2 = w20.x*ha.x + w20.y*ha.y + w20.z*ha.z + w20.w*ha.w
                 + w21.x*hb.x + w21.y*hb.y + w21.z*hb.z + w21.w*hb.w;
        float p3 = w30.x*ha.x + w30.y*ha.y + w30.z*ha.z + w30.w*ha.w
                 + w31.x*hb.x + w31.y*hb.y + w31.z*hb.z + w31.w*hb.w;
        #pragma unroll
        for (int o = 16; o; o >>= 1) {
            p0 += __shfl_xor_sync(0xffffffffu, p0, o);
            p1 += __shfl_xor_sync(0xffffffffu, p1, o);
            p2 += __shfl_xor_sync(0xffffffffu, p2, o);
            p3 += __shfl_xor_sync(0xffffffffu, p3, o);
        }
        float t0 = sigf_fast(p0), t1 = sigf_fast(p1), t2 = sigf_fast(p2), t3 = sigf_fast(p3);
        a0.x += t0*w00.x + t1*w10.x + t2*w20.x + t3*w30.x;
        a0.y += t0*w00.y + t1*w10.y + t2*w20.y + t3*w30.y;
        a0.z += t0*w00.z + t1*w10.z + t2*w20.z + t3*w30.z;
        a0.w += t0*w00.w + t1*w10.w + t2*w20.w + t3*w30.w;
        a1.x += t0*w01.x + t1*w11.x + t2*w21.x + t3*w31.x;
        a1.y += t0*w01.y + t1*w11.y + t2*w21.y + t3*w31.y;
        a1.z += t0*w01.z + t1*w11.z + t2*w21.z + t3*w31.z;
        a1.w += t0*w01.w + t1*w11.w + t2*w21.w + t3*w31.w;
    }
    int rem = nrows & 3;
    if (gw < rem) {
        const float4* base = x + (size_t)(ngroups * 4 + gw) * 64;
        float4 v0 = base[lane], v1 = base[lane + 32];
        float p = v0.x*ha.x + v0.y*ha.y + v0.z*ha.z + v0.w*ha.w
                + v1.x*hb.x + v1.y*hb.y + v1.z*hb.z + v1.w*hb.w;
        #pragma unroll
        for (int o = 16; o; o >>= 1) p += __shfl_xor_sync(0xffffffffu, p, o);
        float att = sigf_fast(p);
        a0.x += att*v0.x; a0.y += att*v0.y; a0.z += att*v0.z; a0.w += att*v0.w;
        a1.x += att*v1.x; a1.y += att*v1.y; a1.z += att*v1.z; a1.w += att*v1.w;
    }
    block_col_reduce(bacc, t, lane, a0, a1, g_sumax[g]);

    // last finishing block computes h2
    __threadfence();
    __syncthreads();
    if (t == 0) isLast = (atomicAdd(&g_cnt[2 + g], 1u) == (unsigned)(gridDim.x - 1));
    __syncthreads();
    if (isLast) {
        __shared__ float tv[256];
        tv[t] = ((volatile float*)g_sumax[g])[t] * invN;
        __syncthreads();
        float acc = 0.f;
        #pragma unroll 8
        for (int i = 0; i < 256; ++i) acc = fmaf(tv[i], W0[i * 256 + t], acc);
        g_h2[g][t] = tanhf(acc);
    }
}

// ---------------- pass 3: out = sum(sig(att*(x.h2))*att*x) ----------------
__global__ void __launch_bounds__(256) k_out(const float4* __restrict__ x, int nrows, int g) {
    __shared__ float4 h1s[64];
    __shared__ float4 h2s[64];
    __shared__ float bacc[256];
    int t = threadIdx.x;
    bacc[t] = 0.f;
    if (t < 64) { h1s[t] = ((const float4*)g_h1[g])[t]; h2s[t] = ((const float4*)g_h2[g])[t]; }
    __syncthreads();
    int lane = t & 31;
    int gw = (blockIdx.x << 3) + (t >> 5);
    int nW = gridDim.x << 3;
    float4 ha = h1s[lane], hb = h1s[lane + 32];
    float4 ga = h2s[lane], gb = h2s[lane + 32];
    float4 a0 = make_float4(0.f,0.f,0.f,0.f), a1 = make_float4(0.f,0.f,0.f,0.f);
    int ngroups = nrows >> 2;
    for (int gi = gw; gi < ngroups; gi += nW) {
        const float4* base = x + (size_t)gi * 256;
        float4 w00 = base[lane      ], w01 = base[lane +  32];
        float4 w10 = base[lane +  64], w11 = base[lane +  96];
        float4 w20 = base[lane + 128], w21 = base[lane + 160];
        float4 w30 = base[lane + 192], w31 = base[lane + 224];
        float p0 = w00.x*ha.x + w00.y*ha.y + w00.z*ha.z + w00.w*ha.w
                 + w01.x*hb.x + w01.y*hb.y + w01.z*hb.z + w01.w*hb.w;
        float p1 = w10.x*ha.x + w10.y*ha.y + w10.z*ha.z + w10.w*ha.w
                 + w11.x*hb.x + w11.y*hb.y + w11.z*hb.z + w11.w*hb.w;
        float p2 = w20.x*ha.x + w20.y*ha.y + w20.z*ha.z + w20.w*ha.w
                 + w21.x*hb.x + w21.y*hb.y + w21.z*hb.z + w21.w*hb.w;
        float p3 = w30.x*ha.x + w30.y*ha.y + w30.z*ha.z + w30.w*ha.w
                 + w31.x*hb.x + w31.y*hb.y + w31.z*hb.z + w31.w*hb.w;
        float q0 = w00.x*ga.x + w00.y*ga.y + w00.z*ga.z + w00.w*ga.w
                 + w01.x*gb.x + w01.y*gb.y + w01.z*gb.z + w01.w*gb.w;
        float q1 = w10.x*ga.x + w10.y*ga.y + w10.z*ga.z + w10.w*ga.w
                 + w11.x*gb.x + w11.y*gb.y + w11.z*gb.z + w11.w*gb.w;
        float q2 = w20.x*ga.x + w20.y*ga.y + w20.z*ga.z + w20.w*ga.w
                 + w21.x*gb.x + w21.y*gb.y + w21.z*gb.z + w21.w*gb.w;
        float q3 = w30.x*ga.x + w30.y*ga.y + w30.z*ga.z + w30.w*ga.w
                 + w31.x*gb.x + w31.y*gb.y + w31.z*gb.z + w31.w*gb.w;
        #pragma unroll
        for (int o = 16; o; o >>= 1) {
            p0 += __shfl_xor_sync(0xffffffffu, p0, o);
            p1 += __shfl_xor_sync(0xffffffffu, p1, o);
            p2 += __shfl_xor_sync(0xffffffffu, p2, o);
            p3 += __shfl_xor_sync(0xffffffffu, p3, o);
            q0 += __shfl_xor_sync(0xffffffffu, q0, o);
            q1 += __shfl_xor_sync(0xffffffffu, q1, o);
            q2 += __shfl_xor_sync(0xffffffffu, q2, o);
            q3 += __shfl_xor_sync(0xffffffffu, q3, o);
        }
        float t0 = sigf_fast(p0), t1 = sigf_fast(p1), t2 = sigf_fast(p2), t3 = sigf_fast(p3);
        t0 *= sigf_fast(t0 * q0);
        t1 *= sigf_fast(t1 * q1);
        t2 *= sigf_fast(t2 * q2);
        t3 *= sigf_fast(t3 * q3);
        a0.x += t0*w00.x + t1*w10.x + t2*w20.x + t3*w30.x;
        a0.y += t0*w00.y + t1*w10.y + t2*w20.y + t3*w30.y;
        a0.z += t0*w00.z + t1*w10.z + t2*w20.z + t3*w30.z;
        a0.w += t0*w00.w + t1*w10.w + t2*w20.w + t3*w30.w;
        a1.x += t0*w01.x + t1*w11.x + t2*w21.x + t3*w31.x;
        a1.y += t0*w01.y + t1*w11.y + t2*w21.y + t3*w31.y;
        a1.z += t0*w01.z + t1*w11.z + t2*w21.z + t3*w31.z;
        a1.w += t0*w01.w + t1*w11.w + t2*w21.w + t3*w31.w;
    }
    int rem = nrows & 3;
    if (gw < rem) {
        const float4* base = x + (size_t)(ngroups * 4 + gw) * 64;
        float4 v0 = base[lane], v1 = base[lane + 32];
        float p = v0.x*ha.x + v0.y*ha.y + v0.z*ha.z + v0.w*ha.w
                + v1.x*hb.x + v1.y*hb.y + v1.z*hb.z + v1.w*hb.w;
        float q = v0.x*ga.x + v0.y*ga.y + v0.z*ga.z + v0.w*ga.w
                + v1.x*gb.x + v1.y*gb.y + v1.z*gb.z + v1.w*gb.w;
        #pragma unroll
        for (int o = 16; o; o >>= 1) {
            p += __shfl_xor_sync(0xffffffffu, p, o);
            q += __shfl_xor_sync(0xffffffffu, q, o);
        }
        float att = sigf_fast(p);
        float wgt = att * sigf_fast(att * q);
        a0.x += wgt*v0.x; a0.y += wgt*v0.y; a0.z += wgt*v0.z; a0.w += wgt*v0.w;
        a1.x += wgt*v1.x; a1.y += wgt*v1.y; a1.z += wgt*v1.z; a1.w += wgt*v1.w;
    }
    block_col_reduce(bacc, t, lane, a0, a1, g_outv[g]);
}

// ---------------- NTN: w_term (streams W, 16.8MB) + v_term ----------------
__global__ void __launch_bounds__(256) k_ntn(const float* __restrict__ W, const float* __restrict__ V) {
    __shared__ float g1s[16];
    __shared__ float red[8];
    int b = blockIdx.x, t = threadIdx.x;
    float acc = 0.f;
    int f;
    if (b < 512) {
        f = b >> 5;
        int chunk = b & 31;
        if (t < 16) g1s[t] = g_outv[0][(chunk * 16 + t) & 255];
        __syncthreads();
        float o2 = g_outv[1][t];  // e=t and e=t+256 both map to out2[t]
        const float* base = W + ((size_t)f * 512 + chunk * 16) * 512;
        #pragma unroll
        for (int i = 0; i < 16; ++i) {
            const float* wr = base + (size_t)i * 512;
            acc += g1s[i] * (wr[t] + wr[t + 256]);
        }
        acc *= o2;
    } else {
        f = b - 512;
        const float* vf = V + (size_t)f * 1024;
        acc = g_outv[0][t] * (vf[t] + vf[256 + t])
            + g_outv[1][t] * (vf[512 + t] + vf[768 + t]);
    }
    #pragma unroll
    for (int o = 16; o; o >>= 1) acc += __shfl_xor_sync(0xffffffffu, acc, o);
    if ((t & 31) == 0) red[t >> 5] = acc;
    __syncthreads();
    if (t < 8) {
        float s = red[t];
        s += __shfl_xor_sync(0xffu, s, 4);
        s += __shfl_xor_sync(0xffu, s, 2);
        s += __shfl_xor_sync(0xffu, s, 1);
        if (t == 0) atomicAdd(&g_wacc[f], s);
    }
}

// ---------------- final: sigmoid(NTN) -> MLP 16->8->4->2->1 ----------------
__global__ void k_final(const float* __restrict__ b, const float* __restrict__ P0,
                        const float* __restrict__ P1, const float* __restrict__ P2,
                        const float* __restrict__ P3, float* __restrict__ out) {
    int t = threadIdx.x;
    __shared__ float s[16];
    if (t < 16) s[t] = 1.f / (1.f + expf(-(g_wacc[t] + b[t])));
    __syncwarp();
    if (t == 0) {
        float y0[8];
        #pragma unroll
        for (int o = 0; o < 8; ++o) {
            float a = 0.f;
            #pragma unroll
            for (int ff = 0; ff < 16; ++ff) a += s[ff] * P0[o * 16 + ff];
            y0[o] = 1.f / (1.f + expf(-a));
        }
        float y1[4];
        #pragma unroll
        for (int o = 0; o < 4; ++o) {
            float a = 0.f;
            #pragma unroll
            for (int ff = 0; ff < 8; ++ff) a += y0[ff] * P1[o * 8 + ff];
            y1[o] = 1.f / (1.f + expf(-a));
        }
        float y2[2];
        #pragma unroll
        for (int o = 0; o < 2; ++o) {
            float a = 0.f;
            #pragma unroll
            for (int ff = 0; ff < 4; ++ff) a += y1[ff] * P2[o * 4 + ff];
            y2[o] = 1.f / (1.f + expf(-a));
        }
        float a = y2[0] * P3[0] + y2[1] * P3[1];
        out[0] = 1.f / (1.f + expf(-a));
    }
}

extern "C" void kernel_launch(void* const* d_in, const int* in_sizes, int n_in,
                              void* d_out, int out_size) {
    const float* x1 = (const float*)d_in[0];
    const float* x2 = (const float*)d_in[1];
    const float* W0 = (const float*)d_in[2];
    const float* V  = (const float*)d_in[3];
    const float* W  = (const float*)d_in[4];
    const float* bb = (const float*)d_in[5];
    const float* P0 = (const float*)d_in[6];
    const float* P1 = (const float*)d_in[7];
    const float* P2 = (const float*)d_in[8];
    const float* P3 = (const float*)d_in[9];
    int N1 = in_sizes[0] / 256;
    int N2 = in_sizes[1] / 256;
    float* out = (float*)d_out;

    k_zero<<<1, 256>>>();

    // graph 1 (x1): 3 streaming passes; h1/h2 computed by last block of passes 1/2
    k_sum   <<<PGRID, 256>>>((const float4*)x1, N1, 0, W0, 1.f / (float)N1);
    k_attsum<<<PGRID, 256>>>((const float4*)x1, N1, 0, W0, 1.f / (float)N1);
    k_out   <<<PGRID, 256>>>((const float4*)x1, N1, 0);

    // graph 2 (x2) — kept after graph 1 so each graph's passes reuse L2-resident x
    k_sum   <<<PGRID, 256>>>((const float4*)x2, N2, 1, W0, 1.f / (float)N2);
    k_attsum<<<PGRID, 256>>>((const float4*)x2, N2, 1, W0, 1.f / (float)N2);
    k_out   <<<PGRID, 256>>>((const float4*)x2, N2, 1);

    // NTN bilinear + v_term, then tiny MLP head
    k_ntn  <<<528, 256>>>(W, V);
    k_final<<<1, 32>>>(bb, P0, P1, P2, P3, out);
}

// round 9
// speedup vs baseline: 1.7280x; 1.7280x over previous
#include <cuda_runtime.h>
#include <cstdint>
#include <math.h>

// ---------------- scratch (no allocations allowed) ----------------
__device__ __align__(16) float g_sum[2][256];    // pass-1: sum(x)
__device__ __align__(16) float g_sumax[2][256];  // pass-2: sum(att*x)
__device__ __align__(16) float g_outv[2][256];   // pass-3: graph embedding (one head)
__device__ __align__(16) float g_h1[2][256];
__device__ __align__(16) float g_h2[2][256];
__device__ float g_wacc[16];                      // w_term + v_term accumulator

__device__ __forceinline__ float sigf_fast(float z) { return 1.0f / (1.0f + __expf(-z)); }

static const int PGRID = 444;   // 148 SMs * 3 CTAs -> single wave
#define TILE_ROWS 16
#define TILE_F4   (TILE_ROWS * 64)   // 1024 float4 = 16 KB

// ---------------- zero accumulators ----------------
__global__ void k_zero() {
    int t = threadIdx.x;
    g_sum[0][t] = 0.f;  g_sum[1][t] = 0.f;
    g_sumax[0][t] = 0.f; g_sumax[1][t] = 0.f;
    g_outv[0][t] = 0.f;  g_outv[1][t] = 0.f;
    if (t < 16) g_wacc[t] = 0.f;
}

// ---------------- cp.async helpers ----------------
__device__ __forceinline__ void stage_tile(float4* dst, const float4* src) {
    // 1024 float4 staged by 256 threads, 4 cp.async each (16B, L1-bypass)
    int t = threadIdx.x;
    unsigned int s = (unsigned int)__cvta_generic_to_shared(dst + t);
    const float4* g = src + t;
    #pragma unroll
    for (int i = 0; i < 4; ++i) {
        asm volatile("cp.async.cg.shared.global [%0], [%1], 16;"
                     :: "r"(s + i * 256 * 16), "l"(g + i * 256));
    }
}
#define CP_COMMIT()  asm volatile("cp.async.commit_group;" ::: "memory")
#define CP_WAIT1()   asm volatile("cp.async.wait_group 1;" ::: "memory")

// block-level 256-col reduction: per-warp float4 accumulators -> bacc -> global atomics
__device__ __forceinline__ void block_col_reduce(float* bacc, int t, int lane,
                                                 float4 a0, float4 a1, float* gdst) {
    int c = lane * 4;
    atomicAdd(&bacc[c + 0], a0.x); atomicAdd(&bacc[c + 1], a0.y);
    atomicAdd(&bacc[c + 2], a0.z); atomicAdd(&bacc[c + 3], a0.w);
    atomicAdd(&bacc[128 + c + 0], a1.x); atomicAdd(&bacc[128 + c + 1], a1.y);
    atomicAdd(&bacc[128 + c + 2], a1.z); atomicAdd(&bacc[128 + c + 3], a1.w);
    __syncthreads();
    atomicAdd(&gdst[t], bacc[t]);
}

// ---------------- pass 1: column sum of x (cp.async pipelined) ----------------
__global__ void __launch_bounds__(256) k_sum(const float4* __restrict__ x, int nrows, int g) {
    __shared__ __align__(16) float4 buf[2][TILE_F4];
    __shared__ float bacc[256];
    int t = threadIdx.x;
    bacc[t] = 0.f;
    int lane = t & 31, wid = t >> 5;
    float4 a0 = make_float4(0.f,0.f,0.f,0.f), a1 = make_float4(0.f,0.f,0.f,0.f);

    int ntiles = nrows >> 4;
    int parity = 0;
    if ((int)blockIdx.x < ntiles) stage_tile(buf[0], x + (size_t)blockIdx.x * TILE_F4);
    CP_COMMIT();
    for (int tile = blockIdx.x; tile < ntiles; tile += gridDim.x) {
        int nxt = tile + gridDim.x;
        if (nxt < ntiles) stage_tile(buf[parity ^ 1], x + (size_t)nxt * TILE_F4);
        CP_COMMIT();
        CP_WAIT1();
        __syncthreads();
        const float4* row0 = buf[parity] + (wid * 2) * 64;
        const float4* row1 = row0 + 64;
        float4 v00 = row0[lane], v01 = row0[lane + 32];
        float4 v10 = row1[lane], v11 = row1[lane + 32];
        a0.x += v00.x + v10.x; a0.y += v00.y + v10.y;
        a0.z += v00.z + v10.z; a0.w += v00.w + v10.w;
        a1.x += v01.x + v11.x; a1.y += v01.y + v11.y;
        a1.z += v01.z + v11.z; a1.w += v01.w + v11.w;
        __syncthreads();
        parity ^= 1;
    }
    // tail rows
    int full = ntiles << 4;
    int rem = nrows - full;
    int gw = (blockIdx.x << 3) + wid;
    if (gw < rem) {
        const float4* base = x + (size_t)(full + gw) * 64;
        float4 v0 = base[lane], v1 = base[lane + 32];
        a0.x += v0.x; a0.y += v0.y; a0.z += v0.z; a0.w += v0.w;
        a1.x += v1.x; a1.y += v1.y; a1.z += v1.z; a1.w += v1.w;
    }
    __syncthreads();
    block_col_reduce(bacc, t, lane, a0, a1, g_sum[g]);
}

// ---------------- tiny matvec: h = tanh((src/N) @ W0)  (separate, parallel) ----------------
__global__ void __launch_bounds__(256) k_h(const float* __restrict__ W0, float invN, int g, int stage) {
    __shared__ float tv[256];
    __shared__ float part[8][33];
    int t = threadIdx.x;
    const float* src = stage ? g_sumax[g] : g_sum[g];
    tv[t] = src[t] * invN;
    __syncthreads();
    int w = t >> 5, l = t & 31;
    int j = blockIdx.x * 32 + l;
    float acc = 0.f;
    const float* col = W0 + (size_t)(w * 32) * 256 + j;
    #pragma unroll 8
    for (int i = 0; i < 32; ++i) acc = fmaf(tv[w * 32 + i], col[i * 256], acc);
    part[w][l] = acc;
    __syncthreads();
    if (w == 0) {
        float s = 0.f;
        #pragma unroll
        for (int k = 0; k < 8; ++k) s += part[k][l];
        float* dst = stage ? g_h2[g] : g_h1[g];
        dst[j] = tanhf(s);
    }
}

// ---------------- pass 2: att = sigmoid(x.h1); sum(att*x) ----------------
__global__ void __launch_bounds__(256) k_attsum(const float4* __restrict__ x, int nrows, int g) {
    __shared__ __align__(16) float4 buf[2][TILE_F4];
    __shared__ float bacc[256];
    int t = threadIdx.x;
    bacc[t] = 0.f;
    int lane = t & 31, wid = t >> 5;
    float4 ha = ((const float4*)g_h1[g])[lane];
    float4 hb = ((const float4*)g_h1[g])[lane + 32];
    float4 a0 = make_float4(0.f,0.f,0.f,0.f), a1 = make_float4(0.f,0.f,0.f,0.f);

    int ntiles = nrows >> 4;
    int parity = 0;
    if ((int)blockIdx.x < ntiles) stage_tile(buf[0], x + (size_t)blockIdx.x * TILE_F4);
    CP_COMMIT();
    for (int tile = blockIdx.x; tile < ntiles; tile += gridDim.x) {
        int nxt = tile + gridDim.x;
        if (nxt < ntiles) stage_tile(buf[parity ^ 1], x + (size_t)nxt * TILE_F4);
        CP_COMMIT();
        CP_WAIT1();
        __syncthreads();
        const float4* row0 = buf[parity] + (wid * 2) * 64;
        const float4* row1 = row0 + 64;
        float4 v00 = row0[lane], v01 = row0[lane + 32];
        float4 v10 = row1[lane], v11 = row1[lane + 32];
        float p0 = v00.x*ha.x + v00.y*ha.y + v00.z*ha.z + v00.w*ha.w
                 + v01.x*hb.x + v01.y*hb.y + v01.z*hb.z + v01.w*hb.w;
        float p1 = v10.x*ha.x + v10.y*ha.y + v10.z*ha.z + v10.w*ha.w
                 + v11.x*hb.x + v11.y*hb.y + v11.z*hb.z + v11.w*hb.w;
        #pragma unroll
        for (int o = 16; o; o >>= 1) {
            p0 += __shfl_xor_sync(0xffffffffu, p0, o);
            p1 += __shfl_xor_sync(0xffffffffu, p1, o);
        }
        float t0 = sigf_fast(p0), t1 = sigf_fast(p1);
        a0.x += t0*v00.x + t1*v10.x; a0.y += t0*v00.y + t1*v10.y;
        a0.z += t0*v00.z + t1*v10.z; a0.w += t0*v00.w + t1*v10.w;
        a1.x += t0*v01.x + t1*v11.x; a1.y += t0*v01.y + t1*v11.y;
        a1.z += t0*v01.z + t1*v11.z; a1.w += t0*v01.w + t1*v11.w;
        __syncthreads();
        parity ^= 1;
    }
    int full = ntiles << 4;
    int rem = nrows - full;
    int gw = (blockIdx.x << 3) + wid;
    if (gw < rem) {
        const float4* base = x + (size_t)(full + gw) * 64;
        float4 v0 = base[lane], v1 = base[lane + 32];
        float p = v0.x*ha.x + v0.y*ha.y + v0.z*ha.z + v0.w*ha.w
                + v1.x*hb.x + v1.y*hb.y + v1.z*hb.z + v1.w*hb.w;
        #pragma unroll
        for (int o = 16; o; o >>= 1) p += __shfl_xor_sync(0xffffffffu, p, o);
        float att = sigf_fast(p);
        a0.x += att*v0.x; a0.y += att*v0.y; a0.z += att*v0.z; a0.w += att*v0.w;
        a1.x += att*v1.x; a1.y += att*v1.y; a1.z += att*v1.z; a1.w += att*v1.w;
    }
    __syncthreads();
    block_col_reduce(bacc, t, lane, a0, a1, g_sumax[g]);
}

// ---------------- pass 3: out = sum(sig(att*(x.h2))*att*x) ----------------
__global__ void __launch_bounds__(256) k_out(const float4* __restrict__ x, int nrows, int g) {
    __shared__ __align__(16) float4 buf[2][TILE_F4];
    __shared__ float bacc[256];
    int t = threadIdx.x;
    bacc[t] = 0.f;
    int lane = t & 31, wid = t >> 5;
    float4 ha = ((const float4*)g_h1[g])[lane];
    float4 hb = ((const float4*)g_h1[g])[lane + 32];
    float4 ga = ((const float4*)g_h2[g])[lane];
    float4 gb = ((const float4*)g_h2[g])[lane + 32];
    float4 a0 = make_float4(0.f,0.f,0.f,0.f), a1 = make_float4(0.f,0.f,0.f,0.f);

    int ntiles = nrows >> 4;
    int parity = 0;
    if ((int)blockIdx.x < ntiles) stage_tile(buf[0], x + (size_t)blockIdx.x * TILE_F4);
    CP_COMMIT();
    for (int tile = blockIdx.x; tile < ntiles; tile += gridDim.x) {
        int nxt = tile + gridDim.x;
        if (nxt < ntiles) stage_tile(buf[parity ^ 1], x + (size_t)nxt * TILE_F4);
        CP_COMMIT();
        CP_WAIT1();
        __syncthreads();
        const float4* row0 = buf[parity] + (wid * 2) * 64;
        const float4* row1 = row0 + 64;
        float4 v00 = row0[lane], v01 = row0[lane + 32];
        float4 v10 = row1[lane], v11 = row1[lane + 32];
        float p0 = v00.x*ha.x + v00.y*ha.y + v00.z*ha.z + v00.w*ha.w
                 + v01.x*hb.x + v01.y*hb.y + v01.z*hb.z + v01.w*hb.w;
        float p1 = v10.x*ha.x + v10.y*ha.y + v10.z*ha.z + v10.w*ha.w
                 + v11.x*hb.x + v11.y*hb.y + v11.z*hb.z + v11.w*hb.w;
        float q0 = v00.x*ga.x + v00.y*ga.y + v00.z*ga.z + v00.w*ga.w
                 + v01.x*gb.x + v01.y*gb.y + v01.z*gb.z + v01.w*gb.w;
        float q1 = v10.x*ga.x + v10.y*ga.y + v10.z*ga.z + v10.w*ga.w
                 + v11.x*gb.x + v11.y*gb.y + v11.z*gb.z + v11.w*gb.w;
        #pragma unroll
        for (int o = 16; o; o >>= 1) {
            p0 += __shfl_xor_sync(0xffffffffu, p0, o);
            p1 += __shfl_xor_sync(0xffffffffu, p1, o);
            q0 += __shfl_xor_sync(0xffffffffu, q0, o);
            q1 += __shfl_xor_sync(0xffffffffu, q1, o);
        }
        float t0 = sigf_fast(p0), t1 = sigf_fast(p1);
        t0 *= sigf_fast(t0 * q0);
        t1 *= sigf_fast(t1 * q1);
        a0.x += t0*v00.x + t1*v10.x; a0.y += t0*v00.y + t1*v10.y;
        a0.z += t0*v00.z + t1*v10.z; a0.w += t0*v00.w + t1*v10.w;
        a1.x += t0*v01.x + t1*v11.x; a1.y += t0*v01.y + t1*v11.y;
        a1.z += t0*v01.z + t1*v11.z; a1.w += t0*v01.w + t1*v11.w;
        __syncthreads();
        parity ^= 1;
    }
    int full = ntiles << 4;
    int rem = nrows - full;
    int gw = (blockIdx.x << 3) + wid;
    if (gw < rem) {
        const float4* base = x + (size_t)(full + gw) * 64;
        float4 v0 = base[lane], v1 = base[lane + 32];
        float p = v0.x*ha.x + v0.y*ha.y + v0.z*ha.z + v0.w*ha.w
                + v1.x*hb.x + v1.y*hb.y + v1.z*hb.z + v1.w*hb.w;
        float q = v0.x*ga.x + v0.y*ga.y + v0.z*ga.z + v0.w*ga.w
                + v1.x*gb.x + v1.y*gb.y + v1.z*gb.z + v1.w*gb.w;
        #pragma unroll
        for (int o = 16; o; o >>= 1) {
            p += __shfl_xor_sync(0xffffffffu, p, o);
            q += __shfl_xor_sync(0xffffffffu, q, o);
        }
        float att = sigf_fast(p);
        float wgt = att * sigf_fast(att * q);
        a0.x += wgt*v0.x; a0.y += wgt*v0.y; a0.z += wgt*v0.z; a0.w += wgt*v0.w;
        a1.x += wgt*v1.x; a1.y += wgt*v1.y; a1.z += wgt*v1.z; a1.w += wgt*v1.w;
    }
    __syncthreads();
    block_col_reduce(bacc, t, lane, a0, a1, g_outv[g]);
}

// ---------------- NTN: w_term (streams W, 16.8MB) + v_term ----------------
__global__ void __launch_bounds__(256) k_ntn(const float* __restrict__ W, const float* __restrict__ V) {
    __shared__ float g1s[16];
    __shared__ float red[8];
    int b = blockIdx.x, t = threadIdx.x;
    float acc = 0.f;
    int f;
    if (b < 512) {
        f = b >> 5;
        int chunk = b & 31;
        if (t < 16) g1s[t] = g_outv[0][(chunk * 16 + t) & 255];
        __syncthreads();
        float o2 = g_outv[1][t];  // e=t and e=t+256 both map to out2[t]
        const float* base = W + ((size_t)f * 512 + chunk * 16) * 512;
        #pragma unroll
        for (int i = 0; i < 16; ++i) {
            const float* wr = base + (size_t)i * 512;
            acc += g1s[i] * (wr[t] + wr[t + 256]);
        }
        acc *= o2;
    } else {
        f = b - 512;
        const float* vf = V + (size_t)f * 1024;
        acc = g_outv[0][t] * (vf[t] + vf[256 + t])
            + g_outv[1][t] * (vf[512 + t] + vf[768 + t]);
    }
    #pragma unroll
    for (int o = 16; o; o >>= 1) acc += __shfl_xor_sync(0xffffffffu, acc, o);
    if ((t & 31) == 0) red[t >> 5] = acc;
    __syncthreads();
    if (t < 8) {
        float s = red[t];
        s += __shfl_xor_sync(0xffu, s, 4);
        s += __shfl_xor_sync(0xffu, s, 2);
        s += __shfl_xor_sync(0xffu, s, 1);
        if (t == 0) atomicAdd(&g_wacc[f], s);
    }
}

// ---------------- final: sigmoid(NTN) -> MLP 16->8->4->2->1 ----------------
__global__ void k_final(const float* __restrict__ b, const float* __restrict__ P0,
                        const float* __restrict__ P1, const float* __restrict__ P2,
                        const float* __restrict__ P3, float* __restrict__ out) {
    int t = threadIdx.x;
    __shared__ float s[16];
    if (t < 16) s[t] = 1.f / (1.f + expf(-(g_wacc[t] + b[t])));
    __syncwarp();
    if (t == 0) {
        float y0[8];
        #pragma unroll
        for (int o = 0; o < 8; ++o) {
            float a = 0.f;
            #pragma unroll
            for (int ff = 0; ff < 16; ++ff) a += s[ff] * P0[o * 16 + ff];
            y0[o] = 1.f / (1.f + expf(-a));
        }
        float y1[4];
        #pragma unroll
        for (int o = 0; o < 4; ++o) {
            float a = 0.f;
            #pragma unroll
            for (int ff = 0; ff < 8; ++ff) a += y0[ff] * P1[o * 8 + ff];
            y1[o] = 1.f / (1.f + expf(-a));
        }
        float y2[2];
        #pragma unroll
        for (int o = 0; o < 2; ++o) {
            float a = 0.f;
            #pragma unroll
            for (int ff = 0; ff < 4; ++ff) a += y1[ff] * P2[o * 4 + ff];
            y2[o] = 1.f / (1.f + expf(-a));
        }
        float a = y2[0] * P3[0] + y2[1] * P3[1];
        out[0] = 1.f / (1.f + expf(-a));
    }
}

extern "C" void kernel_launch(void* const* d_in, const int* in_sizes, int n_in,
                              void* d_out, int out_size) {
    const float* x1 = (const float*)d_in[0];
    const float* x2 = (const float*)d_in[1];
    const float* W0 = (const float*)d_in[2];
    const float* V  = (const float*)d_in[3];
    const float* W  = (const float*)d_in[4];
    const float* bb = (const float*)d_in[5];
    const float* P0 = (const float*)d_in[6];
    const float* P1 = (const float*)d_in[7];
    const float* P2 = (const float*)d_in[8];
    const float* P3 = (const float*)d_in[9];
    int N1 = in_sizes[0] / 256;
    int N2 = in_sizes[1] / 256;
    float* out = (float*)d_out;

    k_zero<<<1, 256>>>();

    // graph 1 (x1)
    k_sum   <<<PGRID, 256>>>((const float4*)x1, N1, 0);
    k_h     <<<8, 256>>>(W0, 1.f / (float)N1, 0, 0);
    k_attsum<<<PGRID, 256>>>((const float4*)x1, N1, 0);
    k_h     <<<8, 256>>>(W0, 1.f / (float)N1, 0, 1);
    k_out   <<<PGRID, 256>>>((const float4*)x1, N1, 0);

    // graph 2 (x2)
    k_sum   <<<PGRID, 256>>>((const float4*)x2, N2, 1);
    k_h     <<<8, 256>>>(W0, 1.f / (float)N2, 1, 0);
    k_attsum<<<PGRID, 256>>>((const float4*)x2, N2, 1);
    k_h     <<<8, 256>>>(W0, 1.f / (float)N2, 1, 1);
    k_out   <<<PGRID, 256>>>((const float4*)x2, N2, 1);

    // NTN bilinear + v_term, then tiny MLP head
    k_ntn  <<<528, 256>>>(W, V);
    k_final<<<1, 32>>>(bb, P0, P1, P2, P3, out);
}

// round 10
// speedup vs baseline: 1.7398x; 1.0068x over previous
#include <cuda_runtime.h>
#include <cstdint>
#include <math.h>

// ---------------- scratch (no allocations allowed) ----------------
__device__ __align__(16) float g_sum[2][256];    // pass-1: sum(x)
__device__ __align__(16) float g_sumax[2][256];  // pass-2: sum(att*x)
__device__ __align__(16) float g_outv[2][256];   // pass-3: graph embedding (one head)
__device__ __align__(16) float g_h1[2][256];
__device__ __align__(16) float g_h2[2][256];
__device__ float g_wacc[16];                      // w_term + v_term accumulator

__device__ __forceinline__ float sigf_fast(float z) { return 1.0f / (1.0f + __expf(-z)); }

static const int PGRID = 444;   // 148 SMs * 3 CTAs -> single wave
#define TILE_ROWS 16
#define TILE_F4   (TILE_ROWS * 64)       // 1024 float4 = 16 KB
#define STAGES    4
#define DYN_SMEM  (STAGES * TILE_F4 * 16)  // 64 KB

// ---------------- zero accumulators ----------------
__global__ void k_zero() {
    int t = threadIdx.x;
    g_sum[0][t] = 0.f;  g_sum[1][t] = 0.f;
    g_sumax[0][t] = 0.f; g_sumax[1][t] = 0.f;
    g_outv[0][t] = 0.f;  g_outv[1][t] = 0.f;
    if (t < 16) g_wacc[t] = 0.f;
}

// ---------------- cp.async helpers ----------------
__device__ __forceinline__ void stage_tile(float4* dst, const float4* src) {
    // 1024 float4 staged by 256 threads, 4 cp.async each (16B, L1-bypass)
    int t = threadIdx.x;
    unsigned int s = (unsigned int)__cvta_generic_to_shared(dst + t);
    const float4* g = src + t;
    #pragma unroll
    for (int i = 0; i < 4; ++i) {
        asm volatile("cp.async.cg.shared.global [%0], [%1], 16;"
                     :: "r"(s + i * 256 * 16), "l"(g + i * 256));
    }
}
#define CP_COMMIT()  asm volatile("cp.async.commit_group;" ::: "memory")
#define CP_WAIT3()   asm volatile("cp.async.wait_group 3;" ::: "memory")

// block-level 256-col reduction: per-warp float4 accumulators -> bacc -> global atomics
__device__ __forceinline__ void block_col_reduce(float* bacc, int t, int lane,
                                                 float4 a0, float4 a1, float* gdst) {
    int c = lane * 4;
    atomicAdd(&bacc[c + 0], a0.x); atomicAdd(&bacc[c + 1], a0.y);
    atomicAdd(&bacc[c + 2], a0.z); atomicAdd(&bacc[c + 3], a0.w);
    atomicAdd(&bacc[128 + c + 0], a1.x); atomicAdd(&bacc[128 + c + 1], a1.y);
    atomicAdd(&bacc[128 + c + 2], a1.z); atomicAdd(&bacc[128 + c + 3], a1.w);
    __syncthreads();
    atomicAdd(&gdst[t], bacc[t]);
}

// ---------------- pass 1: column sum of x (4-stage cp.async pipeline) ----------------
__global__ void __launch_bounds__(256) k_sum(const float4* __restrict__ x, int nrows, int g) {
    extern __shared__ __align__(16) float4 buf[];   // STAGES * TILE_F4
    __shared__ float bacc[256];
    int t = threadIdx.x;
    bacc[t] = 0.f;
    int lane = t & 31, wid = t >> 5;
    float4 a0 = make_float4(0.f,0.f,0.f,0.f), a1 = make_float4(0.f,0.f,0.f,0.f);

    int ntiles = nrows >> 4;
    #pragma unroll
    for (int j = 0; j < STAGES - 1; ++j) {
        int tl = blockIdx.x + j * gridDim.x;
        if (tl < ntiles) stage_tile(buf + j * TILE_F4, x + (size_t)tl * TILE_F4);
        CP_COMMIT();
    }
    int it = 0;
    for (int tile = blockIdx.x; tile < ntiles; tile += gridDim.x, ++it) {
        int nxt = tile + (STAGES - 1) * gridDim.x;
        if (nxt < ntiles) stage_tile(buf + ((it + STAGES - 1) & (STAGES - 1)) * TILE_F4,
                                     x + (size_t)nxt * TILE_F4);
        CP_COMMIT();
        CP_WAIT3();
        __syncthreads();
        const float4* row0 = buf + (it & (STAGES - 1)) * TILE_F4 + (wid * 2) * 64;
        const float4* row1 = row0 + 64;
        float4 v00 = row0[lane], v01 = row0[lane + 32];
        float4 v10 = row1[lane], v11 = row1[lane + 32];
        a0.x += v00.x + v10.x; a0.y += v00.y + v10.y;
        a0.z += v00.z + v10.z; a0.w += v00.w + v10.w;
        a1.x += v01.x + v11.x; a1.y += v01.y + v11.y;
        a1.z += v01.z + v11.z; a1.w += v01.w + v11.w;
        __syncthreads();
    }
    // tail rows
    int full = ntiles << 4;
    int rem = nrows - full;
    int gw = (blockIdx.x << 3) + wid;
    if (gw < rem) {
        const float4* base = x + (size_t)(full + gw) * 64;
        float4 v0 = base[lane], v1 = base[lane + 32];
        a0.x += v0.x; a0.y += v0.y; a0.z += v0.z; a0.w += v0.w;
        a1.x += v1.x; a1.y += v1.y; a1.z += v1.z; a1.w += v1.w;
    }
    __syncthreads();
    block_col_reduce(bacc, t, lane, a0, a1, g_sum[g]);
}

// ---------------- tiny matvec: h = tanh((src/N) @ W0)  (separate, parallel) ----------------
__global__ void __launch_bounds__(256) k_h(const float* __restrict__ W0, float invN, int g, int stage) {
    __shared__ float tv[256];
    __shared__ float part[8][33];
    int t = threadIdx.x;
    const float* src = stage ? g_sumax[g] : g_sum[g];
    tv[t] = src[t] * invN;
    __syncthreads();
    int w = t >> 5, l = t & 31;
    int j = blockIdx.x * 32 + l;
    float acc = 0.f;
    const float* col = W0 + (size_t)(w * 32) * 256 + j;
    #pragma unroll 8
    for (int i = 0; i < 32; ++i) acc = fmaf(tv[w * 32 + i], col[i * 256], acc);
    part[w][l] = acc;
    __syncthreads();
    if (w == 0) {
        float s = 0.f;
        #pragma unroll
        for (int k = 0; k < 8; ++k) s += part[k][l];
        float* dst = stage ? g_h2[g] : g_h1[g];
        dst[j] = tanhf(s);
    }
}

// ---------------- pass 2: att = sigmoid(x.h1); sum(att*x) ----------------
__global__ void __launch_bounds__(256) k_attsum(const float4* __restrict__ x, int nrows, int g) {
    extern __shared__ __align__(16) float4 buf[];
    __shared__ float bacc[256];
    int t = threadIdx.x;
    bacc[t] = 0.f;
    int lane = t & 31, wid = t >> 5;
    float4 ha = ((const float4*)g_h1[g])[lane];
    float4 hb = ((const float4*)g_h1[g])[lane + 32];
    float4 a0 = make_float4(0.f,0.f,0.f,0.f), a1 = make_float4(0.f,0.f,0.f,0.f);

    int ntiles = nrows >> 4;
    #pragma unroll
    for (int j = 0; j < STAGES - 1; ++j) {
        int tl = blockIdx.x + j * gridDim.x;
        if (tl < ntiles) stage_tile(buf + j * TILE_F4, x + (size_t)tl * TILE_F4);
        CP_COMMIT();
    }
    int it = 0;
    for (int tile = blockIdx.x; tile < ntiles; tile += gridDim.x, ++it) {
        int nxt = tile + (STAGES - 1) * gridDim.x;
        if (nxt < ntiles) stage_tile(buf + ((it + STAGES - 1) & (STAGES - 1)) * TILE_F4,
                                     x + (size_t)nxt * TILE_F4);
        CP_COMMIT();
        CP_WAIT3();
        __syncthreads();
        const float4* row0 = buf + (it & (STAGES - 1)) * TILE_F4 + (wid * 2) * 64;
        const float4* row1 = row0 + 64;
        float4 v00 = row0[lane], v01 = row0[lane + 32];
        float4 v10 = row1[lane], v11 = row1[lane + 32];
        float p0 = v00.x*ha.x + v00.y*ha.y + v00.z*ha.z + v00.w*ha.w
                 + v01.x*hb.x + v01.y*hb.y + v01.z*hb.z + v01.w*hb.w;
        float p1 = v10.x*ha.x + v10.y*ha.y + v10.z*ha.z + v10.w*ha.w
                 + v11.x*hb.x + v11.y*hb.y + v11.z*hb.z + v11.w*hb.w;
        #pragma unroll
        for (int o = 16; o; o >>= 1) {
            p0 += __shfl_xor_sync(0xffffffffu, p0, o);
            p1 += __shfl_xor_sync(0xffffffffu, p1, o);
        }
        float t0 = sigf_fast(p0), t1 = sigf_fast(p1);
        a0.x += t0*v00.x + t1*v10.x; a0.y += t0*v00.y + t1*v10.y;
        a0.z += t0*v00.z + t1*v10.z; a0.w += t0*v00.w + t1*v10.w;
        a1.x += t0*v01.x + t1*v11.x; a1.y += t0*v01.y + t1*v11.y;
        a1.z += t0*v01.z + t1*v11.z; a1.w += t0*v01.w + t1*v11.w;
        __syncthreads();
    }
    int full = ntiles << 4;
    int rem = nrows - full;
    int gw = (blockIdx.x << 3) + wid;
    if (gw < rem) {
        const float4* base = x + (size_t)(full + gw) * 64;
        float4 v0 = base[lane], v1 = base[lane + 32];
        float p = v0.x*ha.x + v0.y*ha.y + v0.z*ha.z + v0.w*ha.w
                + v1.x*hb.x + v1.y*hb.y + v1.z*hb.z + v1.w*hb.w;
        #pragma unroll
        for (int o = 16; o; o >>= 1) p += __shfl_xor_sync(0xffffffffu, p, o);
        float att = sigf_fast(p);
        a0.x += att*v0.x; a0.y += att*v0.y; a0.z += att*v0.z; a0.w += att*v0.w;
        a1.x += att*v1.x; a1.y += att*v1.y; a1.z += att*v1.z; a1.w += att*v1.w;
    }
    __syncthreads();
    block_col_reduce(bacc, t, lane, a0, a1, g_sumax[g]);
}

// ---------------- pass 3: out = sum(sig(att*(x.h2))*att*x) ----------------
__global__ void __launch_bounds__(256) k_out(const float4* __restrict__ x, int nrows, int g) {
    extern __shared__ __align__(16) float4 buf[];
    __shared__ float bacc[256];
    int t = threadIdx.x;
    bacc[t] = 0.f;
    int lane = t & 31, wid = t >> 5;
    float4 ha = ((const float4*)g_h1[g])[lane];
    float4 hb = ((const float4*)g_h1[g])[lane + 32];
    float4 ga = ((const float4*)g_h2[g])[lane];
    float4 gb = ((const float4*)g_h2[g])[lane + 32];
    float4 a0 = make_float4(0.f,0.f,0.f,0.f), a1 = make_float4(0.f,0.f,0.f,0.f);

    int ntiles = nrows >> 4;
    #pragma unroll
    for (int j = 0; j < STAGES - 1; ++j) {
        int tl = blockIdx.x + j * gridDim.x;
        if (tl < ntiles) stage_tile(buf + j * TILE_F4, x + (size_t)tl * TILE_F4);
        CP_COMMIT();
    }
    int it = 0;
    for (int tile = blockIdx.x; tile < ntiles; tile += gridDim.x, ++it) {
        int nxt = tile + (STAGES - 1) * gridDim.x;
        if (nxt < ntiles) stage_tile(buf + ((it + STAGES - 1) & (STAGES - 1)) * TILE_F4,
                                     x + (size_t)nxt * TILE_F4);
        CP_COMMIT();
        CP_WAIT3();
        __syncthreads();
        const float4* row0 = buf + (it & (STAGES - 1)) * TILE_F4 + (wid * 2) * 64;
        const float4* row1 = row0 + 64;
        float4 v00 = row0[lane], v01 = row0[lane + 32];
        float4 v10 = row1[lane], v11 = row1[lane + 32];
        float p0 = v00.x*ha.x + v00.y*ha.y + v00.z*ha.z + v00.w*ha.w
                 + v01.x*hb.x + v01.y*hb.y + v01.z*hb.z + v01.w*hb.w;
        float p1 = v10.x*ha.x + v10.y*ha.y + v10.z*ha.z + v10.w*ha.w
                 + v11.x*hb.x + v11.y*hb.y + v11.z*hb.z + v11.w*hb.w;
        float q0 = v00.x*ga.x + v00.y*ga.y + v00.z*ga.z + v00.w*ga.w
                 + v01.x*gb.x + v01.y*gb.y + v01.z*gb.z + v01.w*gb.w;
        float q1 = v10.x*ga.x + v10.y*ga.y + v10.z*ga.z + v10.w*ga.w
                 + v11.x*gb.x + v11.y*gb.y + v11.z*gb.z + v11.w*gb.w;
        #pragma unroll
        for (int o = 16; o; o >>= 1) {
            p0 += __shfl_xor_sync(0xffffffffu, p0, o);
            p1 += __shfl_xor_sync(0xffffffffu, p1, o);
            q0 += __shfl_xor_sync(0xffffffffu, q0, o);
            q1 += __shfl_xor_sync(0xffffffffu, q1, o);
        }
        float t0 = sigf_fast(p0), t1 = sigf_fast(p1);
        t0 *= sigf_fast(t0 * q0);
        t1 *= sigf_fast(t1 * q1);
        a0.x += t0*v00.x + t1*v10.x; a0.y += t0*v00.y + t1*v10.y;
        a0.z += t0*v00.z + t1*v10.z; a0.w += t0*v00.w + t1*v10.w;
        a1.x += t0*v01.x + t1*v11.x; a1.y += t0*v01.y + t1*v11.y;
        a1.z += t0*v01.z + t1*v11.z; a1.w += t0*v01.w + t1*v11.w;
        __syncthreads();
    }
    int full = ntiles << 4;
    int rem = nrows - full;
    int gw = (blockIdx.x << 3) + wid;
    if (gw < rem) {
        const float4* base = x + (size_t)(full + gw) * 64;
        float4 v0 = base[lane], v1 = base[lane + 32];
        float p = v0.x*ha.x + v0.y*ha.y + v0.z*ha.z + v0.w*ha.w
                + v1.x*hb.x + v1.y*hb.y + v1.z*hb.z + v1.w*hb.w;
        float q = v0.x*ga.x + v0.y*ga.y + v0.z*ga.z + v0.w*ga.w
                + v1.x*gb.x + v1.y*gb.y + v1.z*gb.z + v1.w*gb.w;
        #pragma unroll
        for (int o = 16; o; o >>= 1) {
            p += __shfl_xor_sync(0xffffffffu, p, o);
            q += __shfl_xor_sync(0xffffffffu, q, o);
        }
        float att = sigf_fast(p);
        float wgt = att * sigf_fast(att * q);
        a0.x += wgt*v0.x; a0.y += wgt*v0.y; a0.z += wgt*v0.z; a0.w += wgt*v0.w;
        a1.x += wgt*v1.x; a1.y += wgt*v1.y; a1.z += wgt*v1.z; a1.w += wgt*v1.w;
    }
    __syncthreads();
    block_col_reduce(bacc, t, lane, a0, a1, g_outv[g]);
}

// ---------------- NTN: w_term (streams W, 16.8MB) + v_term ----------------
__global__ void __launch_bounds__(256) k_ntn(const float* __restrict__ W, const float* __restrict__ V) {
    __shared__ float g1s[16];
    __shared__ float red[8];
    int b = blockIdx.x, t = threadIdx.x;
    float acc = 0.f;
    int f;
    if (b < 512) {
        f = b >> 5;
        int chunk = b & 31;
        if (t < 16) g1s[t] = g_outv[0][(chunk * 16 + t) & 255];
        __syncthreads();
        float o2 = g_outv[1][t];  // e=t and e=t+256 both map to out2[t]
        const float* base = W + ((size_t)f * 512 + chunk * 16) * 512;
        #pragma unroll
        for (int i = 0; i < 16; ++i) {
            const float* wr = base + (size_t)i * 512;
            acc += g1s[i] * (wr[t] + wr[t + 256]);
        }
        acc *= o2;
    } else {
        f = b - 512;
        const float* vf = V + (size_t)f * 1024;
        acc = g_outv[0][t] * (vf[t] + vf[256 + t])
            + g_outv[1][t] * (vf[512 + t] + vf[768 + t]);
    }
    #pragma unroll
    for (int o = 16; o; o >>= 1) acc += __shfl_xor_sync(0xffffffffu, acc, o);
    if ((t & 31) == 0) red[t >> 5] = acc;
    __syncthreads();
    if (t < 8) {
        float s = red[t];
        s += __shfl_xor_sync(0xffu, s, 4);
        s += __shfl_xor_sync(0xffu, s, 2);
        s += __shfl_xor_sync(0xffu, s, 1);
        if (t == 0) atomicAdd(&g_wacc[f], s);
    }
}

// ---------------- final: sigmoid(NTN) -> MLP 16->8->4->2->1 ----------------
__global__ void k_final(const float* __restrict__ b, const float* __restrict__ P0,
                        const float* __restrict__ P1, const float* __restrict__ P2,
                        const float* __restrict__ P3, float* __restrict__ out) {
    int t = threadIdx.x;
    __shared__ float s[16];
    if (t < 16) s[t] = 1.f / (1.f + expf(-(g_wacc[t] + b[t])));
    __syncwarp();
    if (t == 0) {
        float y0[8];
        #pragma unroll
        for (int o = 0; o < 8; ++o) {
            float a = 0.f;
            #pragma unroll
            for (int ff = 0; ff < 16; ++ff) a += s[ff] * P0[o * 16 + ff];
            y0[o] = 1.f / (1.f + expf(-a));
        }
        float y1[4];
        #pragma unroll
        for (int o = 0; o < 4; ++o) {
            float a = 0.f;
            #pragma unroll
            for (int ff = 0; ff < 8; ++ff) a += y0[ff] * P1[o * 8 + ff];
            y1[o] = 1.f / (1.f + expf(-a));
        }
        float y2[2];
        #pragma unroll
        for (int o = 0; o < 2; ++o) {
            float a = 0.f;
            #pragma unroll
            for (int ff = 0; ff < 4; ++ff) a += y1[ff] * P2[o * 4 + ff];
            y2[o] = 1.f / (1.f + expf(-a));
        }
        float a = y2[0] * P3[0] + y2[1] * P3[1];
        out[0] = 1.f / (1.f + expf(-a));
    }
}

extern "C" void kernel_launch(void* const* d_in, const int* in_sizes, int n_in,
                              void* d_out, int out_size) {
    const float* x1 = (const float*)d_in[0];
    const float* x2 = (const float*)d_in[1];
    const float* W0 = (const float*)d_in[2];
    const float* V  = (const float*)d_in[3];
    const float* W  = (const float*)d_in[4];
    const float* bb = (const float*)d_in[5];
    const float* P0 = (const float*)d_in[6];
    const float* P1 = (const float*)d_in[7];
    const float* P2 = (const float*)d_in[8];
    const float* P3 = (const float*)d_in[9];
    int N1 = in_sizes[0] / 256;
    int N2 = in_sizes[1] / 256;
    float* out = (float*)d_out;

    // raise dynamic smem cap (attribute set only — no allocation, capture-safe)
    static int attr_done = 0;
    if (!attr_done) {
        cudaFuncSetAttribute(k_sum,    cudaFuncAttributeMaxDynamicSharedMemorySize, DYN_SMEM);
        cudaFuncSetAttribute(k_attsum, cudaFuncAttributeMaxDynamicSharedMemorySize, DYN_SMEM);
        cudaFuncSetAttribute(k_out,    cudaFuncAttributeMaxDynamicSharedMemorySize, DYN_SMEM);
        attr_done = 1;
    }

    k_zero<<<1, 256>>>();

    // graph 1 (x1)
    k_sum   <<<PGRID, 256, DYN_SMEM>>>((const float4*)x1, N1, 0);
    k_h     <<<8, 256>>>(W0, 1.f / (float)N1, 0, 0);
    k_attsum<<<PGRID, 256, DYN_SMEM>>>((const float4*)x1, N1, 0);
    k_h     <<<8, 256>>>(W0, 1.f / (float)N1, 0, 1);
    k_out   <<<PGRID, 256, DYN_SMEM>>>((const float4*)x1, N1, 0);

    // graph 2 (x2)
    k_sum   <<<PGRID, 256, DYN_SMEM>>>((const float4*)x2, N2, 1);
    k_h     <<<8, 256>>>(W0, 1.f / (float)N2, 1, 0);
    k_attsum<<<PGRID, 256, DYN_SMEM>>>((const float4*)x2, N2, 1);
    k_h     <<<8, 256>>>(W0, 1.f / (float)N2, 1, 1);
    k_out   <<<PGRID, 256, DYN_SMEM>>>((const float4*)x2, N2, 1);

    // NTN bilinear + v_term, then tiny MLP head
    k_ntn  <<<528, 256>>>(W, V);
    k_final<<<1, 32>>>(bb, P0, P1, P2, P3, out);
}